// round 14
// baseline (speedup 1.0000x reference)
#include <cuda_runtime.h>
#include <cuda_fp16.h>
#include <math.h>
#include <stdint.h>

#define S_LEN 4096
#define D_IN  2048
#define NH    16
#define DH    128
#define HD    2048
#define GM 4096
#define GN 2048
#define GK 2048

// ---------------- scratch (device globals: no allocation allowed) ----------
__device__ float g_inv[64];
__device__ float g_cos[(size_t)S_LEN * (DH/2)];
__device__ float g_sin[(size_t)S_LEN * (DH/2)];
__device__ __half g_xh  [(size_t)S_LEN * D_IN];
__device__ __half g_wqh [(size_t)HD * D_IN];
__device__ __half g_wkh [(size_t)HD * D_IN];
__device__ __half g_wvh [(size_t)HD * D_IN];
__device__ __half g_woh [(size_t)D_IN * HD];
__device__ __half g_qh  [(size_t)S_LEN * HD];
__device__ __half g_kh  [(size_t)S_LEN * HD];
__device__ __half g_vh  [(size_t)S_LEN * HD];
__device__ __half g_aoh [(size_t)S_LEN * HD];

// ---------------- PTX helpers ------------------------------------------------
__device__ __forceinline__ uint32_t smem_u32(const void* p) {
    uint32_t a;
    asm("{ .reg .u64 t; cvta.to.shared.u64 t, %1; cvt.u32.u64 %0, t; }"
        : "=r"(a) : "l"(p));
    return a;
}
__device__ __forceinline__ void cpa16(uint32_t dst, const void* src) {
    asm volatile("cp.async.cg.shared.global [%0], [%1], 16;" :: "r"(dst), "l"(src));
}
__device__ __forceinline__ void cpa_commit() { asm volatile("cp.async.commit_group;"); }
__device__ __forceinline__ void cpa_wait0()  { asm volatile("cp.async.wait_group 0;"); }

__device__ __forceinline__ void ldsm4(uint32_t r[4], uint32_t addr) {
    asm volatile("ldmatrix.sync.aligned.m8n8.x4.shared.b16 {%0,%1,%2,%3}, [%4];"
        : "=r"(r[0]), "=r"(r[1]), "=r"(r[2]), "=r"(r[3]) : "r"(addr));
}
__device__ __forceinline__ void ldsm4t(uint32_t r[4], uint32_t addr) {
    asm volatile("ldmatrix.sync.aligned.m8n8.x4.trans.shared.b16 {%0,%1,%2,%3}, [%4];"
        : "=r"(r[0]), "=r"(r[1]), "=r"(r[2]), "=r"(r[3]) : "r"(addr));
}
__device__ __forceinline__ void mma16816h(float c[4], const uint32_t a[4],
                                          uint32_t b0, uint32_t b1) {
    asm volatile(
        "mma.sync.aligned.m16n8k16.row.col.f32.f16.f16.f32 "
        "{%0,%1,%2,%3}, {%4,%5,%6,%7}, {%8,%9}, {%0,%1,%2,%3};"
        : "+f"(c[0]), "+f"(c[1]), "+f"(c[2]), "+f"(c[3])
        : "r"(a[0]), "r"(a[1]), "r"(a[2]), "r"(a[3]), "r"(b0), "r"(b1));
}
__device__ __forceinline__ uint32_t packh(float a, float b) {
    __half2 t = __floats2half2_rn(a, b);
    return *(uint32_t*)&t;
}

// ---------------- fused fp32 -> fp16 conversion (all 5 tensors) ----------------
#define N4W (HD * D_IN / 4)          // 1048576 = 2^20
#define N4TOT (6 * N4W)
#define N4HALF (N4TOT / 2)

__device__ __forceinline__ void cvt_one(int i,
                                        const float* x, const float* wq,
                                        const float* wk, const float* wv,
                                        const float* wo,
                                        __half* xh, __half* wqh, __half* wkh,
                                        __half* wvh, __half* woh) {
    int seg = i >> 20;
    const float* in;
    __half* out;
    int off;
    if (seg < 2)      { in = x;  out = xh;  off = i; }
    else if (seg == 2){ in = wq; out = wqh; off = i - 2*N4W; }
    else if (seg == 3){ in = wk; out = wkh; off = i - 3*N4W; }
    else if (seg == 4){ in = wv; out = wvh; off = i - 4*N4W; }
    else              { in = wo; out = woh; off = i - 5*N4W; }
    float4 v = ((const float4*)in)[off];
    ((uint32_t*)out)[2*off]   = packh(v.x, v.y);
    ((uint32_t*)out)[2*off+1] = packh(v.z, v.w);
}

__global__ void cvt_all_kernel(const float* __restrict__ x,
                               const float* __restrict__ wq,
                               const float* __restrict__ wk,
                               const float* __restrict__ wv,
                               const float* __restrict__ wo,
                               __half* __restrict__ xh,
                               __half* __restrict__ wqh,
                               __half* __restrict__ wkh,
                               __half* __restrict__ wvh,
                               __half* __restrict__ woh) {
    int i = blockIdx.x * blockDim.x + threadIdx.x;
    if (i >= N4HALF) return;
    cvt_one(i,          x, wq, wk, wv, wo, xh, wqh, wkh, wvh, woh);
    cvt_one(i + N4HALF, x, wq, wk, wv, wo, xh, wqh, wkh, wvh, woh);
}

// ---------------- RoPE tables ---------------------------------------------------
__global__ void rope_inv_kernel() {
    int kp = threadIdx.x;   // 0..63
    if (kp < 64)
        g_inv[kp] = (float)pow(10000.0, -(double)(2*kp) / (double)DH);
}
__global__ void rope_table_kernel() {
    int idx = blockIdx.x * blockDim.x + threadIdx.x;
    if (idx >= S_LEN * (DH/2)) return;
    int row = idx >> 6;
    int kp  = idx & 63;
    float fr = (float)row * g_inv[kp];
    g_cos[idx] = cosf(fr);
    g_sin[idx] = sinf(fr);
}

// ---------------- shared GEMM tiling constants ----------------------------------
#define KS   64
#define ROWB 144                 // 128B data + 16B pad
#define OPB  (128*ROWB)          // 18432
#define QSTB (2*OPB)             // 36864 per stage
#define QGSM (2*QSTB)            // 73728 (2-stage proven best)

// ---------------- merged QKV GEMM: fp16 single-pass + fused RoPE + scale --------
__global__ void __launch_bounds__(256, 2) qkv_gemm_kernel(
    const __half* __restrict__ Ah,
    const __half* __restrict__ Wq, const __half* __restrict__ Wk,
    const __half* __restrict__ Wv,
    __half* __restrict__ Qo, __half* __restrict__ Ko, __half* __restrict__ Vo)
{
    extern __shared__ char smraw[];
    const uint32_t sb = smem_u32(smraw);
    const int tid = threadIdx.x;
    const int w   = tid >> 5;
    const int l   = tid & 31;
    const int wm  = w & 3;
    const int wn  = w >> 2;
    const int m0  = blockIdx.y * 128;
    const int which = blockIdx.x >> 4;          // 0=q 1=k 2=v
    const int n0  = (blockIdx.x & 15) * 128;

    const __half* B = (which == 0) ? Wq : (which == 1) ? Wk : Wv;
    __half* Out     = (which == 0) ? Qo : (which == 1) ? Ko : Vo;

    const __half* ops[2] = { Ah + (size_t)m0 * GK, B + (size_t)n0 * GK };

    float acc[2][8][4];
#pragma unroll
    for (int a = 0; a < 2; a++)
#pragma unroll
        for (int b = 0; b < 8; b++)
#pragma unroll
            for (int c = 0; c < 4; c++) acc[a][b][c] = 0.f;

#pragma unroll
    for (int op = 0; op < 2; op++)
#pragma unroll
        for (int it = 0; it < 4; it++) {
            const int rem = it * 256 + tid;
            const int r = rem >> 3, ch = rem & 7;
            cpa16(sb + op*OPB + r*ROWB + ch*16, ops[op] + (size_t)r * GK + ch*8);
        }
    cpa_commit();

    const int a_row = wm*32 + (l & 15);
    const int a_kc  = (l >> 4) * 8;
    const int b_row = wn*64 + (l & 7) + ((l >> 4) << 3);
    const int b_kc  = ((l >> 3) & 1) * 8;

    const int NSLAB = GK / KS;   // 32
    for (int s = 0; s < NSLAB; s++) {
        const int buf = s & 1;
        cpa_wait0();
        __syncthreads();
        if (s + 1 < NSLAB) {
            const int k0 = (s + 1) * KS;
            const uint32_t dst = sb + (buf ^ 1) * QSTB;
#pragma unroll
            for (int op = 0; op < 2; op++)
#pragma unroll
                for (int it = 0; it < 4; it++) {
                    const int rem = it * 256 + tid;
                    const int r = rem >> 3, ch = rem & 7;
                    cpa16(dst + op*OPB + r*ROWB + ch*16,
                          ops[op] + (size_t)r*GK + k0 + ch*8);
                }
            cpa_commit();
        }
        const uint32_t base = sb + buf * QSTB;
#pragma unroll
        for (int ks = 0; ks < 4; ks++) {
            uint32_t ah[2][4];
#pragma unroll
            for (int mt = 0; mt < 2; mt++) {
                uint32_t aaddr = base + (a_row + mt*16) * ROWB + (ks*16 + a_kc) * 2;
                ldsm4(ah[mt], aaddr);
            }
#pragma unroll
            for (int np = 0; np < 4; np++) {
                uint32_t bh[4];
                uint32_t baddr = base + OPB + (b_row + np*16) * ROWB + (ks*16 + b_kc) * 2;
                ldsm4(bh, baddr);
#pragma unroll
                for (int mt = 0; mt < 2; mt++) {
                    mma16816h(acc[mt][np*2+0], ah[mt], bh[0], bh[1]);
                    mma16816h(acc[mt][np*2+1], ah[mt], bh[2], bh[3]);
                }
            }
        }
        __syncthreads();
    }

    // ---- epilogue: RoPE (+softmax scale * log2e folded into q), fp16 store ----
    const float qscale = (which == 0) ? 0.12751745f : 1.0f;
#pragma unroll
    for (int mt = 0; mt < 2; mt++) {
        const int row = m0 + wm*32 + mt*16 + (l >> 2);
#pragma unroll
        for (int nt = 0; nt < 8; nt++) {
            const int gcol = n0 + wn*64 + nt*8 + (l & 3) * 2;   // even
            float a0 = acc[mt][nt][0], a1 = acc[mt][nt][1];
            float b0 = acc[mt][nt][2], b1 = acc[mt][nt][3];
            if (which < 2) {
                const int kp = (gcol & (DH - 1)) >> 1;
                float c0 = g_cos[(size_t)row * 64 + kp];
                float s0 = g_sin[(size_t)row * 64 + kp];
                float c1 = g_cos[(size_t)(row + 8) * 64 + kp];
                float s1 = g_sin[(size_t)(row + 8) * 64 + kp];
                float t0 = a0 * c0 - a1 * s0; a1 = a1 * c0 + a0 * s0; a0 = t0;
                float t1 = b0 * c1 - b1 * s1; b1 = b1 * c1 + b0 * s1; b0 = t1;
                a0 *= qscale; a1 *= qscale; b0 *= qscale; b1 *= qscale;
            }
            *(uint32_t*)&Out[(size_t)row * HD + gcol]       = packh(a0, a1);
            *(uint32_t*)&Out[(size_t)(row + 8) * HD + gcol] = packh(b0, b1);
        }
    }
}

// ---------------- output-projection GEMM (fp16 single-pass, fp32 out) ----------
__global__ void __launch_bounds__(256, 2) gemm_mma_kernel(
    const __half* __restrict__ Ah, const __half* __restrict__ Bh,
    float* __restrict__ C)
{
    extern __shared__ char smraw[];
    const uint32_t sb = smem_u32(smraw);
    const int tid = threadIdx.x;
    const int w   = tid >> 5;
    const int l   = tid & 31;
    const int wm  = w & 3;
    const int wn  = w >> 2;
    const int m0  = blockIdx.y * 128;
    const int n0  = blockIdx.x * 128;

    const __half* ops[2] = { Ah + (size_t)m0 * GK, Bh + (size_t)n0 * GK };

    float acc[2][8][4];
#pragma unroll
    for (int a = 0; a < 2; a++)
#pragma unroll
        for (int b = 0; b < 8; b++)
#pragma unroll
            for (int c = 0; c < 4; c++) acc[a][b][c] = 0.f;

#pragma unroll
    for (int op = 0; op < 2; op++)
#pragma unroll
        for (int it = 0; it < 4; it++) {
            const int rem = it * 256 + tid;
            const int r = rem >> 3, ch = rem & 7;
            cpa16(sb + op*OPB + r*ROWB + ch*16, ops[op] + (size_t)r * GK + ch*8);
        }
    cpa_commit();

    const int a_row = wm*32 + (l & 15);
    const int a_kc  = (l >> 4) * 8;
    const int b_row = wn*64 + (l & 7) + ((l >> 4) << 3);
    const int b_kc  = ((l >> 3) & 1) * 8;

    const int NSLAB = GK / KS;
    for (int s = 0; s < NSLAB; s++) {
        const int buf = s & 1;
        cpa_wait0();
        __syncthreads();
        if (s + 1 < NSLAB) {
            const int k0 = (s + 1) * KS;
            const uint32_t dst = sb + (buf ^ 1) * QSTB;
#pragma unroll
            for (int op = 0; op < 2; op++)
#pragma unroll
                for (int it = 0; it < 4; it++) {
                    const int rem = it * 256 + tid;
                    const int r = rem >> 3, ch = rem & 7;
                    cpa16(dst + op*OPB + r*ROWB + ch*16,
                          ops[op] + (size_t)r*GK + k0 + ch*8);
                }
            cpa_commit();
        }
        const uint32_t base = sb + buf * QSTB;
#pragma unroll
        for (int ks = 0; ks < 4; ks++) {
            uint32_t ah[2][4];
#pragma unroll
            for (int mt = 0; mt < 2; mt++) {
                uint32_t aaddr = base + (a_row + mt*16) * ROWB + (ks*16 + a_kc) * 2;
                ldsm4(ah[mt], aaddr);
            }
#pragma unroll
            for (int np = 0; np < 4; np++) {
                uint32_t bh[4];
                uint32_t baddr = base + OPB + (b_row + np*16) * ROWB + (ks*16 + b_kc) * 2;
                ldsm4(bh, baddr);
#pragma unroll
                for (int mt = 0; mt < 2; mt++) {
                    mma16816h(acc[mt][np*2+0], ah[mt], bh[0], bh[1]);
                    mma16816h(acc[mt][np*2+1], ah[mt], bh[2], bh[3]);
                }
            }
        }
        __syncthreads();
    }

#pragma unroll
    for (int mt = 0; mt < 2; mt++) {
        const int row = m0 + wm*32 + mt*16 + (l >> 2);
#pragma unroll
        for (int nt = 0; nt < 8; nt++) {
            const int col = n0 + wn*64 + nt*8 + (l & 3) * 2;
            float2 v0 = make_float2(acc[mt][nt][0], acc[mt][nt][1]);
            float2 v1 = make_float2(acc[mt][nt][2], acc[mt][nt][3]);
            *(float2*)&C[(size_t)row * GN + col]       = v0;
            *(float2*)&C[(size_t)(row + 8) * GN + col] = v1;
        }
    }
}

// ---------------- tensor-core flash attention (fp16, causal, paired tiles) ------
#define QROWB 272
#define QTILE (128*QROWB)         // 34816
#define KROWB 272
#define KOPB  (64*KROWB)          // 17408
#define KSTB  (2*KOPB)            // 34816
#define ASMEM (QTILE + 2*KSTB)    // 104448

__device__ __forceinline__ void attn_load_kv(
    uint32_t dstbase,
    const __half* __restrict__ kh, const __half* __restrict__ vh,
    int kvbase, int tid)
{
#pragma unroll
    for (int i = 0; i < 8; i++) {
        const int op  = i >> 2;
        const int rem = (i & 3) * 256 + tid;
        const int row = rem >> 4;
        const int col = rem & 15;
        const __half* src = (op == 0) ? kh : vh;
        cpa16(dstbase + op*KOPB + row*KROWB + col*16,
              src + (size_t)(kvbase + row) * HD + col*8);
    }
    cpa_commit();
}

__global__ void __launch_bounds__(256, 2) attn_mma_kernel(
    const __half* __restrict__ Qh, const __half* __restrict__ Kh,
    const __half* __restrict__ Vh, __half* __restrict__ Oh)
{
    extern __shared__ char smraw[];
    const uint32_t sb = smem_u32(smraw);
    const uint32_t kvb0 = sb + QTILE;
    const int tid = threadIdx.x;
    const int w = tid >> 5, l = tid & 31;
    const int h  = blockIdx.y;
    const int lq = l >> 2;
    const int lc = (l & 3) * 2;

    const size_t hoff = (size_t)h * DH;
    const __half* kh = Kh + hoff;
    const __half* vh = Vh + hoff;
    const __half* qhp = Qh + hoff;

    const uint32_t qaddr0 = sb + (w*16 + (l & 15)) * QROWB + ((l >> 4) * 8) * 2;
    const int NT = S_LEN / 128;   // 32

#pragma unroll 1
    for (int half = 0; half < 2; half++) {
        const int qb = (half == 0) ? (NT - 1 - blockIdx.x) : blockIdx.x;
        const int R = qb * 128 + w * 16;

#pragma unroll
        for (int i = 0; i < 8; i++) {
            const int rem = i * 256 + tid;
            const int r = rem >> 4, ch = rem & 15;
            cpa16(sb + r*QROWB + ch*16,
                  qhp + (size_t)(qb*128 + r) * HD + ch*8);
        }
        cpa_commit();

        float O_[16][4];
#pragma unroll
        for (int nb = 0; nb < 16; nb++)
#pragma unroll
            for (int e = 0; e < 4; e++) O_[nb][e] = 0.f;
        float mrow0 = -INFINITY, mrow1 = -INFINITY;
        float lrow0 = 0.f, lrow1 = 0.f;

        const int nkv = 2 * qb + 2;
        attn_load_kv(kvb0, kh, vh, 0, tid);

        for (int jb = 0; jb < nkv; jb++) {
            const uint32_t base = kvb0 + (jb & 1) * KSTB;
            cpa_wait0();
            __syncthreads();
            if (jb + 1 < nkv)
                attn_load_kv(kvb0 + ((jb + 1) & 1) * KSTB, kh, vh, (jb + 1) * 64, tid);

            const int kvb = jb * 64;
            const bool active = (kvb <= R + 15);
            if (active) {
                float S_[8][4];
#pragma unroll
                for (int nb = 0; nb < 8; nb++)
#pragma unroll
                    for (int e = 0; e < 4; e++) S_[nb][e] = 0.f;

                const uint32_t krow = (l & 7) + ((l >> 4) << 3);
                const uint32_t kcol = ((l >> 3) & 1) * 8;
#pragma unroll
                for (int kc = 0; kc < 8; kc++) {
                    uint32_t qf[4];
                    ldsm4(qf, qaddr0 + kc * 32);
#pragma unroll
                    for (int p = 0; p < 4; p++) {
                        uint32_t bh[4];
                        uint32_t addr = base + (p*16 + krow) * KROWB + (kc*16 + kcol) * 2;
                        ldsm4(bh, addr);
                        mma16816h(S_[p*2+0], qf, bh[0], bh[1]);
                        mma16816h(S_[p*2+1], qf, bh[2], bh[3]);
                    }
                }

                // softmax in base-2 (scale*log2e folded into Q)
                const bool domask = (kvb + 63 > R);
                float mx0 = -INFINITY, mx1 = -INFINITY;
                if (domask) {
#pragma unroll
                    for (int nb = 0; nb < 8; nb++) {
                        const int colb = kvb + nb*8 + lc;
#pragma unroll
                        for (int e = 0; e < 4; e++) {
                            int row = R + lq + (e >> 1) * 8;
                            int col = colb + (e & 1);
                            float v = (col > row) ? -INFINITY : S_[nb][e];
                            S_[nb][e] = v;
                            if (e < 2) mx0 = fmaxf(mx0, v); else mx1 = fmaxf(mx1, v);
                        }
                    }
                } else {
#pragma unroll
                    for (int nb = 0; nb < 8; nb++) {
                        mx0 = fmaxf(mx0, fmaxf(S_[nb][0], S_[nb][1]));
                        mx1 = fmaxf(mx1, fmaxf(S_[nb][2], S_[nb][3]));
                    }
                }
                mx0 = fmaxf(mx0, __shfl_xor_sync(0xffffffffu, mx0, 1));
                mx0 = fmaxf(mx0, __shfl_xor_sync(0xffffffffu, mx0, 2));
                mx1 = fmaxf(mx1, __shfl_xor_sync(0xffffffffu, mx1, 1));
                mx1 = fmaxf(mx1, __shfl_xor_sync(0xffffffffu, mx1, 2));

                // warp-uniform fast path: running max unchanged -> no rescale
                const bool noresc =
                    __all_sync(0xffffffffu, (mx0 <= mrow0) && (mx1 <= mrow1));

                float mn0, mn1, cr0 = 1.f, cr1 = 1.f;
                if (noresc) {
                    mn0 = mrow0; mn1 = mrow1;
                } else {
                    mn0 = fmaxf(mrow0, mx0);
                    mn1 = fmaxf(mrow1, mx1);
                    cr0 = exp2f(mrow0 - mn0);
                    cr1 = exp2f(mrow1 - mn1);
                    mrow0 = mn0; mrow1 = mn1;
                }

                float ls0 = 0.f, ls1 = 0.f;
#pragma unroll
                for (int nb = 0; nb < 8; nb++) {
                    float p0 = exp2f(S_[nb][0] - mn0);
                    float p1 = exp2f(S_[nb][1] - mn0);
                    float p2 = exp2f(S_[nb][2] - mn1);
                    float p3 = exp2f(S_[nb][3] - mn1);
                    S_[nb][0] = p0; S_[nb][1] = p1; S_[nb][2] = p2; S_[nb][3] = p3;
                    ls0 += p0 + p1; ls1 += p2 + p3;
                }
                ls0 += __shfl_xor_sync(0xffffffffu, ls0, 1);
                ls0 += __shfl_xor_sync(0xffffffffu, ls0, 2);
                ls1 += __shfl_xor_sync(0xffffffffu, ls1, 1);
                ls1 += __shfl_xor_sync(0xffffffffu, ls1, 2);

                if (noresc) {
                    lrow0 += ls0;
                    lrow1 += ls1;
                } else {
                    lrow0 = lrow0 * cr0 + ls0;
                    lrow1 = lrow1 * cr1 + ls1;
#pragma unroll
                    for (int nb = 0; nb < 16; nb++) {
                        O_[nb][0] *= cr0; O_[nb][1] *= cr0;
                        O_[nb][2] *= cr1; O_[nb][3] *= cr1;
                    }
                }

                uint32_t aP[4][4];
#pragma unroll
                for (int kj = 0; kj < 4; kj++) {
#pragma unroll
                    for (int hf = 0; hf < 2; hf++) {
                        const int nb = kj*2 + hf;
                        aP[kj][hf*2+0] = packh(S_[nb][0], S_[nb][1]);
                        aP[kj][hf*2+1] = packh(S_[nb][2], S_[nb][3]);
                    }
                }

                const uint32_t vrow = (l & 15);
                const uint32_t vcol = ((l >> 4) << 3);
#pragma unroll
                for (int kj = 0; kj < 4; kj++) {
#pragma unroll
                    for (int p = 0; p < 8; p++) {
                        uint32_t vf[4];
                        uint32_t addr = base + KOPB + (kj*16 + vrow) * KROWB + (p*16 + vcol) * 2;
                        ldsm4t(vf, addr);
                        mma16816h(O_[p*2+0], aP[kj], vf[0], vf[1]);
                        mma16816h(O_[p*2+1], aP[kj], vf[2], vf[3]);
                    }
                }
            }
            __syncthreads();
        }

        const float li0 = 1.f / lrow0;
        const float li1 = 1.f / lrow1;
        const size_t ra = (size_t)(R + lq) * HD + hoff;
        const size_t rb = (size_t)(R + lq + 8) * HD + hoff;
#pragma unroll
        for (int nb = 0; nb < 16; nb++) {
            const int c = nb*8 + lc;
            *(uint32_t*)&Oh[ra + c] = packh(O_[nb][0] * li0, O_[nb][1] * li0);
            *(uint32_t*)&Oh[rb + c] = packh(O_[nb][2] * li1, O_[nb][3] * li1);
        }
    }
}

// ---------------- launch ---------------------------------------------------------
extern "C" void kernel_launch(void* const* d_in, const int* in_sizes, int n_in,
                              void* d_out, int out_size)
{
    const float* x  = (const float*)d_in[0];
    const float* wq = (const float*)d_in[2];
    const float* wk = (const float*)d_in[3];
    const float* wv = (const float*)d_in[4];
    const float* wo = (const float*)d_in[5];
    float* out = (float*)d_out;

    __half *xh, *wqh, *wkh, *wvh, *woh;
    __half *qh, *kh, *vh, *aoh;
    cudaGetSymbolAddress((void**)&xh,   g_xh);
    cudaGetSymbolAddress((void**)&wqh,  g_wqh);  cudaGetSymbolAddress((void**)&wkh,  g_wkh);
    cudaGetSymbolAddress((void**)&wvh,  g_wvh);  cudaGetSymbolAddress((void**)&woh,  g_woh);
    cudaGetSymbolAddress((void**)&qh,   g_qh);   cudaGetSymbolAddress((void**)&kh,   g_kh);
    cudaGetSymbolAddress((void**)&vh,   g_vh);   cudaGetSymbolAddress((void**)&aoh,  g_aoh);

    cudaFuncSetAttribute(qkv_gemm_kernel,
                         cudaFuncAttributeMaxDynamicSharedMemorySize, QGSM);
    cudaFuncSetAttribute(gemm_mma_kernel,
                         cudaFuncAttributeMaxDynamicSharedMemorySize, QGSM);
    cudaFuncSetAttribute(attn_mma_kernel,
                         cudaFuncAttributeMaxDynamicSharedMemorySize, ASMEM);

    rope_inv_kernel<<<1, 64>>>();
    rope_table_kernel<<<(S_LEN*(DH/2) + 255)/256, 256>>>();

    cvt_all_kernel<<<(N4HALF + 255)/256, 256>>>(x, wq, wk, wv, wo,
                                                xh, wqh, wkh, wvh, woh);

    qkv_gemm_kernel<<<dim3(48, GM/128), 256, QGSM>>>(
        xh, wqh, wkh, wvh, qh, kh, vh);

    attn_mma_kernel<<<dim3(S_LEN/256, NH), 256, ASMEM>>>(
        qh, kh, vh, aoh);

    gemm_mma_kernel<<<dim3(GN/128, GM/128), 256, QGSM>>>(aoh, woh, out);
}

// round 15
// speedup vs baseline: 1.0125x; 1.0125x over previous
#include <cuda_runtime.h>
#include <cuda_fp16.h>
#include <math.h>
#include <stdint.h>

#define S_LEN 4096
#define D_IN  2048
#define NH    16
#define DH    128
#define HD    2048
#define GM 4096
#define GN 2048
#define GK 2048

// ---------------- scratch (device globals: no allocation allowed) ----------
__device__ float g_inv[64];
__device__ float g_cos[(size_t)S_LEN * (DH/2)];
__device__ float g_sin[(size_t)S_LEN * (DH/2)];
__device__ __half g_xh  [(size_t)S_LEN * D_IN];
__device__ __half g_wqh [(size_t)HD * D_IN];
__device__ __half g_wkh [(size_t)HD * D_IN];
__device__ __half g_wvh [(size_t)HD * D_IN];
__device__ __half g_woh [(size_t)D_IN * HD];
__device__ __half g_qh  [(size_t)S_LEN * HD];
__device__ __half g_kh  [(size_t)S_LEN * HD];
__device__ __half g_vh  [(size_t)S_LEN * HD];
__device__ __half g_aoh [(size_t)S_LEN * HD];

// ---------------- PTX helpers ------------------------------------------------
__device__ __forceinline__ uint32_t smem_u32(const void* p) {
    uint32_t a;
    asm("{ .reg .u64 t; cvta.to.shared.u64 t, %1; cvt.u32.u64 %0, t; }"
        : "=r"(a) : "l"(p));
    return a;
}
__device__ __forceinline__ void cpa16(uint32_t dst, const void* src) {
    asm volatile("cp.async.cg.shared.global [%0], [%1], 16;" :: "r"(dst), "l"(src));
}
__device__ __forceinline__ void cpa_commit() { asm volatile("cp.async.commit_group;"); }
__device__ __forceinline__ void cpa_wait0()  { asm volatile("cp.async.wait_group 0;"); }

__device__ __forceinline__ void ldsm4(uint32_t r[4], uint32_t addr) {
    asm volatile("ldmatrix.sync.aligned.m8n8.x4.shared.b16 {%0,%1,%2,%3}, [%4];"
        : "=r"(r[0]), "=r"(r[1]), "=r"(r[2]), "=r"(r[3]) : "r"(addr));
}
__device__ __forceinline__ void ldsm4t(uint32_t r[4], uint32_t addr) {
    asm volatile("ldmatrix.sync.aligned.m8n8.x4.trans.shared.b16 {%0,%1,%2,%3}, [%4];"
        : "=r"(r[0]), "=r"(r[1]), "=r"(r[2]), "=r"(r[3]) : "r"(addr));
}
__device__ __forceinline__ void mma16816h(float c[4], const uint32_t a[4],
                                          uint32_t b0, uint32_t b1) {
    asm volatile(
        "mma.sync.aligned.m16n8k16.row.col.f32.f16.f16.f32 "
        "{%0,%1,%2,%3}, {%4,%5,%6,%7}, {%8,%9}, {%0,%1,%2,%3};"
        : "+f"(c[0]), "+f"(c[1]), "+f"(c[2]), "+f"(c[3])
        : "r"(a[0]), "r"(a[1]), "r"(a[2]), "r"(a[3]), "r"(b0), "r"(b1));
}
__device__ __forceinline__ uint32_t packh(float a, float b) {
    __half2 t = __floats2half2_rn(a, b);
    return *(uint32_t*)&t;
}

// ---------------- fused fp32 -> fp16 conversion (all 5 tensors) ----------------
#define N4W (HD * D_IN / 4)          // 1048576 = 2^20
#define N4TOT (6 * N4W)

__global__ void cvt_all_kernel(const float* __restrict__ x,
                               const float* __restrict__ wq,
                               const float* __restrict__ wk,
                               const float* __restrict__ wv,
                               const float* __restrict__ wo,
                               __half* __restrict__ xh,
                               __half* __restrict__ wqh,
                               __half* __restrict__ wkh,
                               __half* __restrict__ wvh,
                               __half* __restrict__ woh) {
    int i = blockIdx.x * blockDim.x + threadIdx.x;
    if (i >= N4TOT) return;
    int seg = i >> 20;
    const float* in;
    __half* out;
    int off;
    if (seg < 2)      { in = x;  out = xh;  off = i; }
    else if (seg == 2){ in = wq; out = wqh; off = i - 2*N4W; }
    else if (seg == 3){ in = wk; out = wkh; off = i - 3*N4W; }
    else if (seg == 4){ in = wv; out = wvh; off = i - 4*N4W; }
    else              { in = wo; out = woh; off = i - 5*N4W; }
    float4 v = ((const float4*)in)[off];
    ((uint32_t*)out)[2*off]   = packh(v.x, v.y);
    ((uint32_t*)out)[2*off+1] = packh(v.z, v.w);
}

// ---------------- RoPE tables ---------------------------------------------------
__global__ void rope_inv_kernel() {
    int kp = threadIdx.x;   // 0..63
    if (kp < 64)
        g_inv[kp] = (float)pow(10000.0, -(double)(2*kp) / (double)DH);
}
__global__ void rope_table_kernel() {
    int idx = blockIdx.x * blockDim.x + threadIdx.x;
    if (idx >= S_LEN * (DH/2)) return;
    int row = idx >> 6;
    int kp  = idx & 63;
    float fr = (float)row * g_inv[kp];
    g_cos[idx] = cosf(fr);
    g_sin[idx] = sinf(fr);
}

// ---------------- shared GEMM tiling constants ----------------------------------
#define KS   64
#define ROWB 144                 // 128B data + 16B pad
#define OPB  (128*ROWB)          // 18432
#define QSTB (2*OPB)             // 36864 per stage
#define QGSM (2*QSTB)            // 73728 (2-stage proven best)

// ---------------- merged QKV GEMM: fp16 single-pass + fused RoPE + scale --------
// Single barrier per K-slab: the top barrier both publishes the fresh cp.async
// data and guarantees the to-be-overwritten buffer (read in iteration s-1) is
// no longer in use. Loop-end barrier removed (redundant by program order).
__global__ void __launch_bounds__(256, 2) qkv_gemm_kernel(
    const __half* __restrict__ Ah,
    const __half* __restrict__ Wq, const __half* __restrict__ Wk,
    const __half* __restrict__ Wv,
    __half* __restrict__ Qo, __half* __restrict__ Ko, __half* __restrict__ Vo)
{
    extern __shared__ char smraw[];
    const uint32_t sb = smem_u32(smraw);
    const int tid = threadIdx.x;
    const int w   = tid >> 5;
    const int l   = tid & 31;
    const int wm  = w & 3;
    const int wn  = w >> 2;
    const int m0  = blockIdx.y * 128;
    const int which = blockIdx.x >> 4;          // 0=q 1=k 2=v
    const int n0  = (blockIdx.x & 15) * 128;

    const __half* B = (which == 0) ? Wq : (which == 1) ? Wk : Wv;
    __half* Out     = (which == 0) ? Qo : (which == 1) ? Ko : Vo;

    const __half* ops[2] = { Ah + (size_t)m0 * GK, B + (size_t)n0 * GK };

    float acc[2][8][4];
#pragma unroll
    for (int a = 0; a < 2; a++)
#pragma unroll
        for (int b = 0; b < 8; b++)
#pragma unroll
            for (int c = 0; c < 4; c++) acc[a][b][c] = 0.f;

#pragma unroll
    for (int op = 0; op < 2; op++)
#pragma unroll
        for (int it = 0; it < 4; it++) {
            const int rem = it * 256 + tid;
            const int r = rem >> 3, ch = rem & 7;
            cpa16(sb + op*OPB + r*ROWB + ch*16, ops[op] + (size_t)r * GK + ch*8);
        }
    cpa_commit();

    const int a_row = wm*32 + (l & 15);
    const int a_kc  = (l >> 4) * 8;
    const int b_row = wn*64 + (l & 7) + ((l >> 4) << 3);
    const int b_kc  = ((l >> 3) & 1) * 8;

    const int NSLAB = GK / KS;   // 32
    for (int s = 0; s < NSLAB; s++) {
        const int buf = s & 1;
        cpa_wait0();
        __syncthreads();
        if (s + 1 < NSLAB) {
            const int k0 = (s + 1) * KS;
            const uint32_t dst = sb + (buf ^ 1) * QSTB;
#pragma unroll
            for (int op = 0; op < 2; op++)
#pragma unroll
                for (int it = 0; it < 4; it++) {
                    const int rem = it * 256 + tid;
                    const int r = rem >> 3, ch = rem & 7;
                    cpa16(dst + op*OPB + r*ROWB + ch*16,
                          ops[op] + (size_t)r*GK + k0 + ch*8);
                }
            cpa_commit();
        }
        const uint32_t base = sb + buf * QSTB;
#pragma unroll
        for (int ks = 0; ks < 4; ks++) {
            uint32_t ah[2][4];
#pragma unroll
            for (int mt = 0; mt < 2; mt++) {
                uint32_t aaddr = base + (a_row + mt*16) * ROWB + (ks*16 + a_kc) * 2;
                ldsm4(ah[mt], aaddr);
            }
#pragma unroll
            for (int np = 0; np < 4; np++) {
                uint32_t bh[4];
                uint32_t baddr = base + OPB + (b_row + np*16) * ROWB + (ks*16 + b_kc) * 2;
                ldsm4(bh, baddr);
#pragma unroll
                for (int mt = 0; mt < 2; mt++) {
                    mma16816h(acc[mt][np*2+0], ah[mt], bh[0], bh[1]);
                    mma16816h(acc[mt][np*2+1], ah[mt], bh[2], bh[3]);
                }
            }
        }
        // no loop-end barrier: next iteration's top barrier provides ordering
    }

    // ---- epilogue: RoPE (+softmax scale * log2e folded into q), fp16 store ----
    const float qscale = (which == 0) ? 0.12751745f : 1.0f;
#pragma unroll
    for (int mt = 0; mt < 2; mt++) {
        const int row = m0 + wm*32 + mt*16 + (l >> 2);
#pragma unroll
        for (int nt = 0; nt < 8; nt++) {
            const int gcol = n0 + wn*64 + nt*8 + (l & 3) * 2;   // even
            float a0 = acc[mt][nt][0], a1 = acc[mt][nt][1];
            float b0 = acc[mt][nt][2], b1 = acc[mt][nt][3];
            if (which < 2) {
                const int kp = (gcol & (DH - 1)) >> 1;
                float c0 = g_cos[(size_t)row * 64 + kp];
                float s0 = g_sin[(size_t)row * 64 + kp];
                float c1 = g_cos[(size_t)(row + 8) * 64 + kp];
                float s1 = g_sin[(size_t)(row + 8) * 64 + kp];
                float t0 = a0 * c0 - a1 * s0; a1 = a1 * c0 + a0 * s0; a0 = t0;
                float t1 = b0 * c1 - b1 * s1; b1 = b1 * c1 + b0 * s1; b0 = t1;
                a0 *= qscale; a1 *= qscale; b0 *= qscale; b1 *= qscale;
            }
            *(uint32_t*)&Out[(size_t)row * HD + gcol]       = packh(a0, a1);
            *(uint32_t*)&Out[(size_t)(row + 8) * HD + gcol] = packh(b0, b1);
        }
    }
}

// ---------------- output-projection GEMM (fp16 single-pass, fp32 out) ----------
__global__ void __launch_bounds__(256, 2) gemm_mma_kernel(
    const __half* __restrict__ Ah, const __half* __restrict__ Bh,
    float* __restrict__ C)
{
    extern __shared__ char smraw[];
    const uint32_t sb = smem_u32(smraw);
    const int tid = threadIdx.x;
    const int w   = tid >> 5;
    const int l   = tid & 31;
    const int wm  = w & 3;
    const int wn  = w >> 2;
    const int m0  = blockIdx.y * 128;
    const int n0  = blockIdx.x * 128;

    const __half* ops[2] = { Ah + (size_t)m0 * GK, Bh + (size_t)n0 * GK };

    float acc[2][8][4];
#pragma unroll
    for (int a = 0; a < 2; a++)
#pragma unroll
        for (int b = 0; b < 8; b++)
#pragma unroll
            for (int c = 0; c < 4; c++) acc[a][b][c] = 0.f;

#pragma unroll
    for (int op = 0; op < 2; op++)
#pragma unroll
        for (int it = 0; it < 4; it++) {
            const int rem = it * 256 + tid;
            const int r = rem >> 3, ch = rem & 7;
            cpa16(sb + op*OPB + r*ROWB + ch*16, ops[op] + (size_t)r * GK + ch*8);
        }
    cpa_commit();

    const int a_row = wm*32 + (l & 15);
    const int a_kc  = (l >> 4) * 8;
    const int b_row = wn*64 + (l & 7) + ((l >> 4) << 3);
    const int b_kc  = ((l >> 3) & 1) * 8;

    const int NSLAB = GK / KS;
    for (int s = 0; s < NSLAB; s++) {
        const int buf = s & 1;
        cpa_wait0();
        __syncthreads();
        if (s + 1 < NSLAB) {
            const int k0 = (s + 1) * KS;
            const uint32_t dst = sb + (buf ^ 1) * QSTB;
#pragma unroll
            for (int op = 0; op < 2; op++)
#pragma unroll
                for (int it = 0; it < 4; it++) {
                    const int rem = it * 256 + tid;
                    const int r = rem >> 3, ch = rem & 7;
                    cpa16(dst + op*OPB + r*ROWB + ch*16,
                          ops[op] + (size_t)r*GK + k0 + ch*8);
                }
            cpa_commit();
        }
        const uint32_t base = sb + buf * QSTB;
#pragma unroll
        for (int ks = 0; ks < 4; ks++) {
            uint32_t ah[2][4];
#pragma unroll
            for (int mt = 0; mt < 2; mt++) {
                uint32_t aaddr = base + (a_row + mt*16) * ROWB + (ks*16 + a_kc) * 2;
                ldsm4(ah[mt], aaddr);
            }
#pragma unroll
            for (int np = 0; np < 4; np++) {
                uint32_t bh[4];
                uint32_t baddr = base + OPB + (b_row + np*16) * ROWB + (ks*16 + b_kc) * 2;
                ldsm4(bh, baddr);
#pragma unroll
                for (int mt = 0; mt < 2; mt++) {
                    mma16816h(acc[mt][np*2+0], ah[mt], bh[0], bh[1]);
                    mma16816h(acc[mt][np*2+1], ah[mt], bh[2], bh[3]);
                }
            }
        }
        // no loop-end barrier
    }

#pragma unroll
    for (int mt = 0; mt < 2; mt++) {
        const int row = m0 + wm*32 + mt*16 + (l >> 2);
#pragma unroll
        for (int nt = 0; nt < 8; nt++) {
            const int col = n0 + wn*64 + nt*8 + (l & 3) * 2;
            float2 v0 = make_float2(acc[mt][nt][0], acc[mt][nt][1]);
            float2 v1 = make_float2(acc[mt][nt][2], acc[mt][nt][3]);
            *(float2*)&C[(size_t)row * GN + col]       = v0;
            *(float2*)&C[(size_t)(row + 8) * GN + col] = v1;
        }
    }
}

// ---------------- tensor-core flash attention (fp16, causal, paired tiles) ------
#define QROWB 272
#define QTILE (128*QROWB)         // 34816
#define KROWB 272
#define KOPB  (64*KROWB)          // 17408
#define KSTB  (2*KOPB)            // 34816
#define ASMEM (QTILE + 2*KSTB)    // 104448

__device__ __forceinline__ void attn_load_kv(
    uint32_t dstbase,
    const __half* __restrict__ kh, const __half* __restrict__ vh,
    int kvbase, int tid)
{
#pragma unroll
    for (int i = 0; i < 8; i++) {
        const int op  = i >> 2;
        const int rem = (i & 3) * 256 + tid;
        const int row = rem >> 4;
        const int col = rem & 15;
        const __half* src = (op == 0) ? kh : vh;
        cpa16(dstbase + op*KOPB + row*KROWB + col*16,
              src + (size_t)(kvbase + row) * HD + col*8);
    }
    cpa_commit();
}

__global__ void __launch_bounds__(256, 2) attn_mma_kernel(
    const __half* __restrict__ Qh, const __half* __restrict__ Kh,
    const __half* __restrict__ Vh, __half* __restrict__ Oh)
{
    extern __shared__ char smraw[];
    const uint32_t sb = smem_u32(smraw);
    const uint32_t kvb0 = sb + QTILE;
    const int tid = threadIdx.x;
    const int w = tid >> 5, l = tid & 31;
    const int h  = blockIdx.y;
    const int lq = l >> 2;
    const int lc = (l & 3) * 2;

    const size_t hoff = (size_t)h * DH;
    const __half* kh = Kh + hoff;
    const __half* vh = Vh + hoff;
    const __half* qhp = Qh + hoff;

    const uint32_t qaddr0 = sb + (w*16 + (l & 15)) * QROWB + ((l >> 4) * 8) * 2;
    const int NT = S_LEN / 128;   // 32

#pragma unroll 1
    for (int half = 0; half < 2; half++) {
        const int qb = (half == 0) ? (NT - 1 - blockIdx.x) : blockIdx.x;
        const int R = qb * 128 + w * 16;

        // Q tile + first KV stage loads (smem free: end-of-half barrier below)
#pragma unroll
        for (int i = 0; i < 8; i++) {
            const int rem = i * 256 + tid;
            const int r = rem >> 4, ch = rem & 15;
            cpa16(sb + r*QROWB + ch*16,
                  qhp + (size_t)(qb*128 + r) * HD + ch*8);
        }
        cpa_commit();

        float O_[16][4];
#pragma unroll
        for (int nb = 0; nb < 16; nb++)
#pragma unroll
            for (int e = 0; e < 4; e++) O_[nb][e] = 0.f;
        float mrow0 = -INFINITY, mrow1 = -INFINITY;
        float lrow0 = 0.f, lrow1 = 0.f;

        const int nkv = 2 * qb + 2;
        attn_load_kv(kvb0, kh, vh, 0, tid);

        for (int jb = 0; jb < nkv; jb++) {
            const uint32_t base = kvb0 + (jb & 1) * KSTB;
            cpa_wait0();
            __syncthreads();
            if (jb + 1 < nkv)
                attn_load_kv(kvb0 + ((jb + 1) & 1) * KSTB, kh, vh, (jb + 1) * 64, tid);

            const int kvb = jb * 64;
            const bool active = (kvb <= R + 15);
            if (active) {
                float S_[8][4];
#pragma unroll
                for (int nb = 0; nb < 8; nb++)
#pragma unroll
                    for (int e = 0; e < 4; e++) S_[nb][e] = 0.f;

                const uint32_t krow = (l & 7) + ((l >> 4) << 3);
                const uint32_t kcol = ((l >> 3) & 1) * 8;
#pragma unroll
                for (int kc = 0; kc < 8; kc++) {
                    uint32_t qf[4];
                    ldsm4(qf, qaddr0 + kc * 32);
#pragma unroll
                    for (int p = 0; p < 4; p++) {
                        uint32_t bh[4];
                        uint32_t addr = base + (p*16 + krow) * KROWB + (kc*16 + kcol) * 2;
                        ldsm4(bh, addr);
                        mma16816h(S_[p*2+0], qf, bh[0], bh[1]);
                        mma16816h(S_[p*2+1], qf, bh[2], bh[3]);
                    }
                }

                // softmax in base-2 (scale*log2e folded into Q)
                const bool domask = (kvb + 63 > R);
                float mx0 = -INFINITY, mx1 = -INFINITY;
                if (domask) {
#pragma unroll
                    for (int nb = 0; nb < 8; nb++) {
                        const int colb = kvb + nb*8 + lc;
#pragma unroll
                        for (int e = 0; e < 4; e++) {
                            int row = R + lq + (e >> 1) * 8;
                            int col = colb + (e & 1);
                            float v = (col > row) ? -INFINITY : S_[nb][e];
                            S_[nb][e] = v;
                            if (e < 2) mx0 = fmaxf(mx0, v); else mx1 = fmaxf(mx1, v);
                        }
                    }
                } else {
#pragma unroll
                    for (int nb = 0; nb < 8; nb++) {
                        mx0 = fmaxf(mx0, fmaxf(S_[nb][0], S_[nb][1]));
                        mx1 = fmaxf(mx1, fmaxf(S_[nb][2], S_[nb][3]));
                    }
                }
                mx0 = fmaxf(mx0, __shfl_xor_sync(0xffffffffu, mx0, 1));
                mx0 = fmaxf(mx0, __shfl_xor_sync(0xffffffffu, mx0, 2));
                mx1 = fmaxf(mx1, __shfl_xor_sync(0xffffffffu, mx1, 1));
                mx1 = fmaxf(mx1, __shfl_xor_sync(0xffffffffu, mx1, 2));
                const float mn0 = fmaxf(mrow0, mx0);
                const float mn1 = fmaxf(mrow1, mx1);
                const float cr0 = exp2f(mrow0 - mn0);
                const float cr1 = exp2f(mrow1 - mn1);
                mrow0 = mn0; mrow1 = mn1;
                float ls0 = 0.f, ls1 = 0.f;
#pragma unroll
                for (int nb = 0; nb < 8; nb++) {
                    float p0 = exp2f(S_[nb][0] - mn0);
                    float p1 = exp2f(S_[nb][1] - mn0);
                    float p2 = exp2f(S_[nb][2] - mn1);
                    float p3 = exp2f(S_[nb][3] - mn1);
                    S_[nb][0] = p0; S_[nb][1] = p1; S_[nb][2] = p2; S_[nb][3] = p3;
                    ls0 += p0 + p1; ls1 += p2 + p3;
                }
                ls0 += __shfl_xor_sync(0xffffffffu, ls0, 1);
                ls0 += __shfl_xor_sync(0xffffffffu, ls0, 2);
                ls1 += __shfl_xor_sync(0xffffffffu, ls1, 1);
                ls1 += __shfl_xor_sync(0xffffffffu, ls1, 2);
                lrow0 = lrow0 * cr0 + ls0;
                lrow1 = lrow1 * cr1 + ls1;

                uint32_t aP[4][4];
#pragma unroll
                for (int kj = 0; kj < 4; kj++) {
#pragma unroll
                    for (int hf = 0; hf < 2; hf++) {
                        const int nb = kj*2 + hf;
                        aP[kj][hf*2+0] = packh(S_[nb][0], S_[nb][1]);
                        aP[kj][hf*2+1] = packh(S_[nb][2], S_[nb][3]);
                    }
                }

#pragma unroll
                for (int nb = 0; nb < 16; nb++) {
                    O_[nb][0] *= cr0; O_[nb][1] *= cr0;
                    O_[nb][2] *= cr1; O_[nb][3] *= cr1;
                }

                const uint32_t vrow = (l & 15);
                const uint32_t vcol = ((l >> 4) << 3);
#pragma unroll
                for (int kj = 0; kj < 4; kj++) {
#pragma unroll
                    for (int p = 0; p < 8; p++) {
                        uint32_t vf[4];
                        uint32_t addr = base + KOPB + (kj*16 + vrow) * KROWB + (p*16 + vcol) * 2;
                        ldsm4t(vf, addr);
                        mma16816h(O_[p*2+0], aP[kj], vf[0], vf[1]);
                        mma16816h(O_[p*2+1], aP[kj], vf[2], vf[3]);
                    }
                }
            }
            // no per-iteration end barrier (next top barrier orders reuse)
        }
        // end-of-half barrier: next half reloads Q/KV smem regions
        __syncthreads();

        const float li0 = 1.f / lrow0;
        const float li1 = 1.f / lrow1;
        const size_t ra = (size_t)(R + lq) * HD + hoff;
        const size_t rb = (size_t)(R + lq + 8) * HD + hoff;
#pragma unroll
        for (int nb = 0; nb < 16; nb++) {
            const int c = nb*8 + lc;
            *(uint32_t*)&Oh[ra + c] = packh(O_[nb][0] * li0, O_[nb][1] * li0);
            *(uint32_t*)&Oh[rb + c] = packh(O_[nb][2] * li1, O_[nb][3] * li1);
        }
    }
}

// ---------------- launch ---------------------------------------------------------
extern "C" void kernel_launch(void* const* d_in, const int* in_sizes, int n_in,
                              void* d_out, int out_size)
{
    const float* x  = (const float*)d_in[0];
    const float* wq = (const float*)d_in[2];
    const float* wk = (const float*)d_in[3];
    const float* wv = (const float*)d_in[4];
    const float* wo = (const float*)d_in[5];
    float* out = (float*)d_out;

    __half *xh, *wqh, *wkh, *wvh, *woh;
    __half *qh, *kh, *vh, *aoh;
    cudaGetSymbolAddress((void**)&xh,   g_xh);
    cudaGetSymbolAddress((void**)&wqh,  g_wqh);  cudaGetSymbolAddress((void**)&wkh,  g_wkh);
    cudaGetSymbolAddress((void**)&wvh,  g_wvh);  cudaGetSymbolAddress((void**)&woh,  g_woh);
    cudaGetSymbolAddress((void**)&qh,   g_qh);   cudaGetSymbolAddress((void**)&kh,   g_kh);
    cudaGetSymbolAddress((void**)&vh,   g_vh);   cudaGetSymbolAddress((void**)&aoh,  g_aoh);

    cudaFuncSetAttribute(qkv_gemm_kernel,
                         cudaFuncAttributeMaxDynamicSharedMemorySize, QGSM);
    cudaFuncSetAttribute(gemm_mma_kernel,
                         cudaFuncAttributeMaxDynamicSharedMemorySize, QGSM);
    cudaFuncSetAttribute(attn_mma_kernel,
                         cudaFuncAttributeMaxDynamicSharedMemorySize, ASMEM);

    rope_inv_kernel<<<1, 64>>>();
    rope_table_kernel<<<(S_LEN*(DH/2) + 255)/256, 256>>>();

    cvt_all_kernel<<<(N4TOT + 255)/256, 256>>>(x, wq, wk, wv, wo,
                                               xh, wqh, wkh, wvh, woh);

    qkv_gemm_kernel<<<dim3(48, GM/128), 256, QGSM>>>(
        xh, wqh, wkh, wvh, qh, kh, vh);

    attn_mma_kernel<<<dim3(S_LEN/256, NH), 256, ASMEM>>>(
        qh, kh, vh, aoh);

    gemm_mma_kernel<<<dim3(GN/128, GM/128), 256, QGSM>>>(aoh, woh, out);
}